// round 9
// baseline (speedup 1.0000x reference)
#include <cuda_runtime.h>
#include <cuda_bf16.h>
#include <cstdint>

// Problem shapes (fixed)
#define BATCH_M   8192      // B*S
#define DIM_K     2048      // IN
#define DIM_N     2048      // OUT
#define ID_DIM    64
#define NW_ELEMS  (DIM_N * DIM_K)

#if defined(__CUDA_ARCH_FEAT_SM103_ALL) || defined(__CUDA_ARCH_FEAT_SM100_ALL) || \
    defined(__CUDA_ARCH_FEAT_SM101_ALL) || defined(__CUDA_ARCH_FEAT_SM110_ALL)
#define HAS_TC 1
#else
#define HAS_TC 0
#endif

// ---------------- scratch ----------------
__device__ __nv_bfloat16 g_Whi[NW_ELEMS];
__device__ __nv_bfloat16 g_Wlo[NW_ELEMS];
__device__ __nv_bfloat16 g_Xhi[BATCH_M * DIM_K];
__device__ __nv_bfloat16 g_Xlo[BATCH_M * DIM_K];
__device__ float         g_bias[DIM_N];
__device__ int           g_flagW[8];    // per-256-row W group, counts to 64
__device__ int           g_flagX[64];   // per-128-row X block, counts to 1

// ---------------- PTX helpers ----------------
__device__ __forceinline__ uint32_t smem_u32(const void* p) {
    uint32_t a;
    asm("{ .reg .u64 t; cvta.to.shared.u64 t, %1; cvt.u32.u64 %0, t; }" : "=r"(a) : "l"(p));
    return a;
}
__device__ __forceinline__ void wait_flag(const int* p, int target) {
    int v;
    do {
        asm volatile("ld.acquire.gpu.global.b32 %0, [%1];" : "=r"(v) : "l"(p) : "memory");
        if (v < target) __nanosleep(256);
    } while (v < target);
}
#if HAS_TC
__device__ __forceinline__ uint32_t elect_one() {
    uint32_t p;
    asm volatile("{ .reg .pred p; elect.sync _|p, 0xFFFFFFFF; selp.b32 %0,1,0,p; }" : "=r"(p));
    return p;
}
#define MBAR_INIT(addr, cnt) \
    asm volatile("mbarrier.init.shared.b64 [%0], %1;" :: "r"(addr), "r"(cnt) : "memory")
#define MBAR_WAIT(addr, par) do {                                              \
    uint32_t _m = (addr), _p = (par), _d;                                      \
    asm volatile("{ .reg .pred p; mbarrier.try_wait.parity.acquire.cta.shared::cta.b64 p, [%1], %2; selp.b32 %0,1,0,p; }" \
        : "=r"(_d) : "r"(_m), "r"(_p) : "memory");                             \
    if (!_d) {                                                                 \
        asm volatile("{ .reg .pred P1; WL%=: mbarrier.try_wait.parity.acquire.cta.shared::cta.b64 P1, [%0], %1, 0x989680; @P1 bra.uni WD%=; bra.uni WL%=; WD%=: }" \
            :: "r"(_m), "r"(_p) : "memory");                                   \
    } } while (0)
#define TC_COMMIT(addr) \
    asm volatile("tcgen05.commit.cta_group::1.mbarrier::arrive::one.shared::cluster.b64 [%0];" :: "r"(addr) : "memory")
#define TC_ALLOC(saddr, n) \
    asm volatile("tcgen05.alloc.cta_group::1.sync.aligned.shared::cta.b32 [%0], %1;" :: "r"(saddr), "r"(n) : "memory")
#define TC_DEALLOC(t, n) \
    asm volatile("tcgen05.dealloc.cta_group::1.sync.aligned.b32 %0, %1;" :: "r"(t), "r"(n))
#define TC_RELINQ() asm volatile("tcgen05.relinquish_alloc_permit.cta_group::1.sync.aligned;")
#define TC_WAIT_LD() asm volatile("tcgen05.wait::ld.sync.aligned;" ::: "memory")
#define TC_FENCE_AFTER() asm volatile("tcgen05.fence::after_thread_sync;" ::: "memory")

#define TC_LD_X32(r, ta)                                                        \
    asm volatile("tcgen05.ld.sync.aligned.32x32b.x32.b32 "                      \
        "{%0,%1,%2,%3,%4,%5,%6,%7,%8,%9,%10,%11,%12,%13,%14,%15,"               \
        "%16,%17,%18,%19,%20,%21,%22,%23,%24,%25,%26,%27,%28,%29,%30,%31}, [%32];" \
        : "=r"((r)[0]),"=r"((r)[1]),"=r"((r)[2]),"=r"((r)[3]),                  \
          "=r"((r)[4]),"=r"((r)[5]),"=r"((r)[6]),"=r"((r)[7]),                  \
          "=r"((r)[8]),"=r"((r)[9]),"=r"((r)[10]),"=r"((r)[11]),                \
          "=r"((r)[12]),"=r"((r)[13]),"=r"((r)[14]),"=r"((r)[15]),              \
          "=r"((r)[16]),"=r"((r)[17]),"=r"((r)[18]),"=r"((r)[19]),              \
          "=r"((r)[20]),"=r"((r)[21]),"=r"((r)[22]),"=r"((r)[23]),              \
          "=r"((r)[24]),"=r"((r)[25]),"=r"((r)[26]),"=r"((r)[27]),              \
          "=r"((r)[28]),"=r"((r)[29]),"=r"((r)[30]),"=r"((r)[31])               \
        : "r"(ta))

static constexpr uint64_t DESC_BASE_SW128 =
    (uint64_t(2) << 61) | (uint64_t(1) << 46) | (uint64_t(64) << 32) | (uint64_t(1) << 16);
__device__ __forceinline__ uint64_t mk_desc(uint32_t a) {
    return DESC_BASE_SW128 | ((uint64_t)(a >> 4) & 0x3FFF);
}
__device__ __forceinline__ void mma_f16_ss(uint32_t d, uint64_t ad, uint64_t bd,
                                           uint32_t idesc, bool acc) {
    uint32_t en = acc ? 1u : 0u;
    asm volatile(
        "{ .reg .pred p; setp.ne.u32 p, %4, 0;\n\t"
        "tcgen05.mma.cta_group::1.kind::f16 [%0], %1, %2, %3, {%5,%5,%5,%5}, p; }"
        :: "r"(d), "l"(ad), "l"(bd), "r"(idesc), "r"(en), "r"(0u) : "memory");
}
__device__ __forceinline__ void cp16(uint32_t dst, const void* src) {
    asm volatile("cp.async.cg.shared.global [%0], [%1], 16;" :: "r"(dst), "l"(src));
}
#define CP_ARRIVE(addr) \
    asm volatile("cp.async.mbarrier.arrive.noinc.shared.b64 [%0];" :: "r"(addr) : "memory")
#endif  // HAS_TC

// ---------------------------------------------------------------------------
// Kernel A: bias + flag reset (strictly precedes the fused kernel in stream).
// ---------------------------------------------------------------------------
__global__ void build_bias(const float* __restrict__ P, const float* __restrict__ coef,
                           float* __restrict__ out, int n) {
    if (blockIdx.x == 0) {
        if (threadIdx.x < 8) g_flagW[threadIdx.x] = 0;
        else if (threadIdx.x < 72) g_flagX[threadIdx.x - 8] = 0;
    }
    __shared__ float c[ID_DIM];
    if (threadIdx.x < ID_DIM) c[threadIdx.x] = coef[threadIdx.x];
    __syncthreads();
    int i = blockIdx.x * blockDim.x + threadIdx.x;
    if (i >= n) return;
    const float4* row = reinterpret_cast<const float4*>(P + (size_t)i * ID_DIM);
    float acc = 0.f;
#pragma unroll
    for (int j = 0; j < 16; ++j) {
        float4 v = row[j];
        acc += v.x * c[4 * j] + v.y * c[4 * j + 1] + v.z * c[4 * j + 2] + v.w * c[4 * j + 3];
    }
    out[i] = acc;
}

// ---------------------------------------------------------------------------
// Kernel B (fused): per-CTA W-slice build (+ X convert on bn==0), flag
// publish, then R6's warp-specialized 128x256 tcgen05 GEMM gated on flags.
// Grid (64 bm, 8 bn): bid = bm + 64*bn, so each bn group's builders form a
// contiguous ascending bid block -> flag waits are deadlock-free.
// ---------------------------------------------------------------------------
#define BM 128
#define BN 256
#define KC 64
#define NCHUNK (DIM_K / KC)          // 32
#define A_TILE 16384
#define B_TILE 32768
#define STAGE_B (2 * A_TILE + 2 * B_TILE)   // 96 KB
#define SM_MBAR 16                   // full0 +0, full1 +8, mdone0 +16, mdone1 +24, alldone +32
#define SM_COEF 512
#define SM_STAGE 1024
#define GEMM_SMEM (SM_STAGE + 2 * STAGE_B)   // 197632

__global__ __launch_bounds__(256, 1)
void gemm_fused(const float* __restrict__ x, const float* __restrict__ P_w,
                const float* __restrict__ wcoef,
                __nv_bfloat16* __restrict__ Xhi, __nv_bfloat16* __restrict__ Xlo,
                __nv_bfloat16* __restrict__ Whi, __nv_bfloat16* __restrict__ Wlo,
                const float* __restrict__ bias, float* __restrict__ C) {
    extern __shared__ char smem[];
    const int tid = threadIdx.x, wid = tid >> 5, lane = tid & 31;
    const int bm = blockIdx.x, bn = blockIdx.y;

    // ================= Phase 0: build (all 256 threads) =================
    {
        float* cf = reinterpret_cast<float*>(smem + SM_COEF);
        if (tid < ID_DIM) cf[tid] = wcoef[tid];
        __syncthreads();
        // W slice: 4 output rows -> 8192 consecutive P_w rows (2.1 MB stream).
        const size_t sliceW = ((size_t)(bn * 256 + bm * 4)) * DIM_K;
        const float4* P4 = reinterpret_cast<const float4*>(P_w) + sliceW * 16;
        const int q = (tid & 15) * 4;
        for (int j = 0; j < 512; j += 4) {
            float p[4];
            int rl[4];
#pragma unroll
            for (int u = 0; u < 4; ++u) {
                int fi = (j + u) * 256 + tid;
                rl[u] = fi >> 4;
                float4 v = P4[fi];
                p[u] = v.x * cf[q] + v.y * cf[q + 1] + v.z * cf[q + 2] + v.w * cf[q + 3];
            }
#pragma unroll
            for (int d = 8; d >= 1; d >>= 1) {
                p[0] += __shfl_xor_sync(0xffffffffu, p[0], d);
                p[1] += __shfl_xor_sync(0xffffffffu, p[1], d);
                p[2] += __shfl_xor_sync(0xffffffffu, p[2], d);
                p[3] += __shfl_xor_sync(0xffffffffu, p[3], d);
            }
            if ((tid & 15) == 0) {
#pragma unroll
                for (int u = 0; u < 4; ++u) {
                    size_t widx = sliceW + rl[u];
                    __nv_bfloat16 h = __float2bfloat16_rn(p[u]);
                    Whi[widx] = h;
                    Wlo[widx] = __float2bfloat16_rn(p[u] - __bfloat162float(h));
                }
            }
        }
        // X convert: bn==0 CTAs convert X block bm (128 rows).
        if (bn == 0) {
            const float4* xp = reinterpret_cast<const float4*>(x) + (size_t)bm * (BM * DIM_K / 4);
            uint2* xh = reinterpret_cast<uint2*>(Xhi + (size_t)bm * BM * DIM_K);
            uint2* xl = reinterpret_cast<uint2*>(Xlo + (size_t)bm * BM * DIM_K);
            for (int j = 0; j < 256; ++j) {
                int fi = j * 256 + tid;
                float4 v = xp[fi];
                float vv[4] = {v.x, v.y, v.z, v.w};
                uint32_t hh[2], ll[2];
#pragma unroll
                for (int w = 0; w < 2; ++w) {
                    __nv_bfloat16 h0 = __float2bfloat16_rn(vv[2 * w]);
                    __nv_bfloat16 h1 = __float2bfloat16_rn(vv[2 * w + 1]);
                    __nv_bfloat16 l0 = __float2bfloat16_rn(vv[2 * w] - __bfloat162float(h0));
                    __nv_bfloat16 l1 = __float2bfloat16_rn(vv[2 * w + 1] - __bfloat162float(h1));
                    hh[w] = ((uint32_t)__bfloat16_as_ushort(h1) << 16) | __bfloat16_as_ushort(h0);
                    ll[w] = ((uint32_t)__bfloat16_as_ushort(l1) << 16) | __bfloat16_as_ushort(l0);
                }
                xh[fi] = make_uint2(hh[0], hh[1]);
                xl[fi] = make_uint2(ll[0], ll[1]);
            }
        }
        __threadfence();
        __syncthreads();
        if (tid == 0) {
            if (bn == 0) atomicExch(&g_flagX[bm], 1);
            atomicAdd(&g_flagW[bn], 1);
        }
    }

    // ================= Phase 1: GEMM =================
#if HAS_TC
    const uint32_t sbase = smem_u32(smem);
    if (wid == 0) {
        TC_ALLOC(sbase, 256);
        TC_RELINQ();
    }
    if (tid == 0) {
        MBAR_INIT(sbase + SM_MBAR + 0, 128);   // full[0]
        MBAR_INIT(sbase + SM_MBAR + 8, 128);   // full[1]
        MBAR_INIT(sbase + SM_MBAR + 16, 1);    // mdone[0]
        MBAR_INIT(sbase + SM_MBAR + 24, 1);    // mdone[1]
        MBAR_INIT(sbase + SM_MBAR + 32, 1);    // alldone
    }
    __syncthreads();
    uint32_t tmem;
    asm volatile("ld.shared.b32 %0, [%1];" : "=r"(tmem) : "r"(sbase));

    const __nv_bfloat16* Ah = Xhi + (size_t)bm * BM * DIM_K;
    const __nv_bfloat16* Al = Xlo + (size_t)bm * BM * DIM_K;
    const __nv_bfloat16* Bh = Whi + (size_t)bn * BN * DIM_K;
    const __nv_bfloat16* Bl = Wlo + (size_t)bn * BN * DIM_K;

    if (wid == 0) {
        // ---------------- consumer: MMA issue ----------------
        if (elect_one()) {
            const uint32_t idesc =
                (1u << 4) | (1u << 7) | (1u << 10) | ((BN / 8) << 17) | ((BM / 16) << 24);
            int fph[2] = {0, 0};
            bool first = true;
            for (int i = 0; i < NCHUNK; ++i) {
                const int s = i & 1;
                MBAR_WAIT(sbase + SM_MBAR + 8 * s, fph[s]);
                fph[s] ^= 1;
                asm volatile("fence.proxy.async.shared::cta;" ::: "memory");
                const uint32_t stg = sbase + SM_STAGE + s * STAGE_B;
                uint64_t dAh = mk_desc(stg);
                uint64_t dAl = mk_desc(stg + A_TILE);
                uint64_t dBh = mk_desc(stg + 2 * A_TILE);
                uint64_t dBl = mk_desc(stg + 2 * A_TILE + B_TILE);
                uint64_t ad[3] = {dAh, dAh, dAl};
                uint64_t bd[3] = {dBh, dBl, dBh};
#pragma unroll
                for (int m = 0; m < 3; ++m)
#pragma unroll
                    for (int ks = 0; ks < 4; ++ks) {
                        mma_f16_ss(tmem, ad[m] + ks * 2, bd[m] + ks * 2, idesc, !first);
                        first = false;
                    }
                TC_COMMIT(sbase + SM_MBAR + 16 + 8 * s);
            }
            // Dedicated final barrier: completes only when ALL prior MMAs drain.
            TC_COMMIT(sbase + SM_MBAR + 32);
            MBAR_WAIT(sbase + SM_MBAR + 32, 0);
        }
    } else if (wid <= 4) {
        // ---------------- producers: 4 warps (128 threads) ----------------
        if (lane == 0) {
            wait_flag(&g_flagW[bn], 64);
            wait_flag(&g_flagX[bm], 1);
        }
        __syncwarp();
        const int ptid = tid - 32;
        int dph[2] = {0, 0};
        for (int i = 0; i < NCHUNK; ++i) {
            const int s = i & 1;
            if (i >= 2) {
                MBAR_WAIT(sbase + SM_MBAR + 16 + 8 * s, dph[s]);
                dph[s] ^= 1;
            }
            const int k0 = i * KC;
            const uint32_t stg = sbase + SM_STAGE + s * STAGE_B;
#pragma unroll
            for (int t = 0; t < 8; ++t) {       // A_hi
                int cid = ptid + t * 128;
                int r = cid >> 3, cc = cid & 7;
                uint32_t off = (uint32_t)(r * 128 + cc * 16);
                cp16(stg + (off ^ ((off >> 3) & 0x70)), Ah + (size_t)r * DIM_K + k0 + cc * 8);
            }
#pragma unroll
            for (int t = 0; t < 8; ++t) {       // A_lo
                int cid = ptid + t * 128;
                int r = cid >> 3, cc = cid & 7;
                uint32_t off = (uint32_t)(r * 128 + cc * 16);
                cp16(stg + A_TILE + (off ^ ((off >> 3) & 0x70)),
                     Al + (size_t)r * DIM_K + k0 + cc * 8);
            }
#pragma unroll
            for (int t = 0; t < 16; ++t) {      // B_hi
                int cid = ptid + t * 128;
                int r = cid >> 3, cc = cid & 7;
                uint32_t off = (uint32_t)(r * 128 + cc * 16);
                cp16(stg + 2 * A_TILE + (off ^ ((off >> 3) & 0x70)),
                     Bh + (size_t)r * DIM_K + k0 + cc * 8);
            }
#pragma unroll
            for (int t = 0; t < 16; ++t) {      // B_lo
                int cid = ptid + t * 128;
                int r = cid >> 3, cc = cid & 7;
                uint32_t off = (uint32_t)(r * 128 + cc * 16);
                cp16(stg + 2 * A_TILE + B_TILE + (off ^ ((off >> 3) & 0x70)),
                     Bl + (size_t)r * DIM_K + k0 + cc * 8);
            }
            CP_ARRIVE(sbase + SM_MBAR + 8 * s);
        }
    }
    __syncthreads();
    TC_FENCE_AFTER();

    // Epilogue: warps 0-3; 8 col-blocks of 32.
    if (wid < 4) {
        float* tbuf = reinterpret_cast<float*>(smem + SM_STAGE + wid * 32 * 33 * 4);
        float* Cb = C + ((size_t)bm * BM) * DIM_N + bn * BN;
        const int rsub = wid * 32;
#pragma unroll 1
        for (int sub = 0; sub < 8; ++sub) {
            const int cb = sub * 32;
            uint32_t regs[32];
            TC_LD_X32(regs, tmem + cb);
            TC_WAIT_LD();
#pragma unroll
            for (int j = 0; j < 32; ++j) tbuf[lane * 33 + j] = __uint_as_float(regs[j]);
            __syncwarp();
            const float bv = bias[bn * BN + cb + lane];
#pragma unroll
            for (int r = 0; r < 32; ++r)
                Cb[(size_t)(rsub + r) * DIM_N + cb + lane] = tbuf[r * 33 + lane] + bv;
            __syncwarp();
        }
    }
    __syncthreads();
    if (wid == 0) TC_DEALLOC(tmem, 256);

#else  // ------------------- SIMT fallback (never runs on GB300) ------------
    if (tid == 0) {
        wait_flag(&g_flagW[bn], 64);
        wait_flag(&g_flagX[bm], 1);
    }
    __syncthreads();
    constexpr int K = DIM_K;
    float (*As)[132] = reinterpret_cast<float(*)[132]>(smem);
    float (*Bs)[132] = reinterpret_cast<float(*)[132]>(smem + 16 * 132 * sizeof(float));
    const int ty = tid >> 4, tx = tid & 15;
    const int lr = tid >> 1;
    const int kof = (tid & 1) * 8;

    for (int half = 0; half < 2; ++half) {
        const __nv_bfloat16* Ah = Xhi + (size_t)bm * BM * K;
        const __nv_bfloat16* Al = Xlo + (size_t)bm * BM * K;
        const __nv_bfloat16* Bh = Whi + ((size_t)bn * BN + half * 128) * K;
        const __nv_bfloat16* Bl = Wlo + ((size_t)bn * BN + half * 128) * K;
        float acc[8][8] = {};
        for (int k0 = 0; k0 < K; k0 += 16) {
            uint4 vh = *reinterpret_cast<const uint4*>(Ah + (size_t)lr * K + k0 + kof);
            uint4 vl = *reinterpret_cast<const uint4*>(Al + (size_t)lr * K + k0 + kof);
#pragma unroll
            for (int w = 0; w < 4; ++w) {
                float2 h = __bfloat1622float2(reinterpret_cast<const __nv_bfloat162*>(&vh)[w]);
                float2 l = __bfloat1622float2(reinterpret_cast<const __nv_bfloat162*>(&vl)[w]);
                As[kof + 2 * w + 0][lr] = h.x + l.x;
                As[kof + 2 * w + 1][lr] = h.y + l.y;
            }
            vh = *reinterpret_cast<const uint4*>(Bh + (size_t)lr * K + k0 + kof);
            vl = *reinterpret_cast<const uint4*>(Bl + (size_t)lr * K + k0 + kof);
#pragma unroll
            for (int w = 0; w < 4; ++w) {
                float2 h = __bfloat1622float2(reinterpret_cast<const __nv_bfloat162*>(&vh)[w]);
                float2 l = __bfloat1622float2(reinterpret_cast<const __nv_bfloat162*>(&vl)[w]);
                Bs[kof + 2 * w + 0][lr] = h.x + l.x;
                Bs[kof + 2 * w + 1][lr] = h.y + l.y;
            }
            __syncthreads();
#pragma unroll
            for (int kk = 0; kk < 16; ++kk) {
                float4 a0 = *reinterpret_cast<const float4*>(&As[kk][ty * 8 + 0]);
                float4 a1 = *reinterpret_cast<const float4*>(&As[kk][ty * 8 + 4]);
                float4 b0 = *reinterpret_cast<const float4*>(&Bs[kk][tx * 8 + 0]);
                float4 b1 = *reinterpret_cast<const float4*>(&Bs[kk][tx * 8 + 4]);
                float af[8] = {a0.x, a0.y, a0.z, a0.w, a1.x, a1.y, a1.z, a1.w};
                float bf[8] = {b0.x, b0.y, b0.z, b0.w, b1.x, b1.y, b1.z, b1.w};
#pragma unroll
                for (int i = 0; i < 8; ++i)
#pragma unroll
                    for (int j = 0; j < 8; ++j)
                        acc[i][j] += af[i] * bf[j];
            }
            __syncthreads();
        }
#pragma unroll
        for (int i = 0; i < 8; ++i) {
            const int row = bm * BM + ty * 8 + i;
            float* Crow = C + (size_t)row * DIM_N + bn * BN + half * 128 + tx * 8;
            const float* brow = bias + bn * BN + half * 128 + tx * 8;
#pragma unroll
            for (int j4 = 0; j4 < 2; ++j4) {
                float4 v;
                v.x = acc[i][j4 * 4 + 0] + brow[j4 * 4 + 0];
                v.y = acc[i][j4 * 4 + 1] + brow[j4 * 4 + 1];
                v.z = acc[i][j4 * 4 + 2] + brow[j4 * 4 + 2];
                v.w = acc[i][j4 * 4 + 3] + brow[j4 * 4 + 3];
                *reinterpret_cast<float4*>(Crow + j4 * 4) = v;
            }
        }
        __syncthreads();
    }
#endif
}

// ---------------------------------------------------------------------------
extern "C" void kernel_launch(void* const* d_in, const int* in_sizes, int n_in,
                              void* d_out, int out_size) {
    const float* x     = (const float*)d_in[0];
    const float* P_w   = (const float*)d_in[1];
    const float* P_b   = (const float*)d_in[2];
    const float* wcoef = (const float*)d_in[3];
    const float* bcoef = (const float*)d_in[4];
    float* out = (float*)d_out;

    __nv_bfloat16 *Whi, *Wlo, *Xhi, *Xlo;
    float* bias;
    cudaGetSymbolAddress((void**)&Whi, g_Whi);
    cudaGetSymbolAddress((void**)&Wlo, g_Wlo);
    cudaGetSymbolAddress((void**)&Xhi, g_Xhi);
    cudaGetSymbolAddress((void**)&Xlo, g_Xlo);
    cudaGetSymbolAddress((void**)&bias, g_bias);

    cudaFuncSetAttribute(gemm_fused, cudaFuncAttributeMaxDynamicSharedMemorySize, GEMM_SMEM);

    // bias + flag reset (stream-ordered before the fused kernel)
    build_bias<<<8, 256>>>(P_b, bcoef, bias, DIM_N);

    dim3 grid(BATCH_M / BM, DIM_N / BN);   // (64 bm, 8 bn); bid = bm + 64*bn
    gemm_fused<<<grid, 256, GEMM_SMEM>>>(x, P_w, wcoef, Xhi, Xlo, Whi, Wlo, bias, out);

    (void)in_sizes; (void)n_in; (void)out_size;
}

// round 10
// speedup vs baseline: 1.8548x; 1.8548x over previous
#include <cuda_runtime.h>
#include <cuda_bf16.h>
#include <cstdint>

// Problem shapes (fixed)
#define BATCH_M   8192      // B*S
#define DIM_K     2048      // IN
#define DIM_N     2048      // OUT
#define ID_DIM    64
#define NW_ELEMS  (DIM_N * DIM_K)

#if defined(__CUDA_ARCH_FEAT_SM103_ALL) || defined(__CUDA_ARCH_FEAT_SM100_ALL) || \
    defined(__CUDA_ARCH_FEAT_SM101_ALL) || defined(__CUDA_ARCH_FEAT_SM110_ALL)
#define HAS_TC 1
#else
#define HAS_TC 0
#endif

// ---------------- scratch ----------------
__device__ __nv_bfloat16 g_Whi[NW_ELEMS];
__device__ __nv_bfloat16 g_Wlo[NW_ELEMS];
__device__ __nv_bfloat16 g_Xhi[BATCH_M * DIM_K];
__device__ __nv_bfloat16 g_Xlo[BATCH_M * DIM_K];
__device__ float         g_bias[DIM_N];
__device__ int           g_flagW[8];    // per 256-row W group; counts to 512

#define BUILD_CTAS_PER_GROUP 512

// ---------------- host-side fork/join resources (created at load time) ------
static cudaStream_t g_s2 = nullptr;
static cudaEvent_t  g_evFork = nullptr, g_evJoin = nullptr;
static bool g_forkOK = false;
namespace {
struct ForkInit {
    ForkInit() {
        g_forkOK = (cudaStreamCreateWithFlags(&g_s2, cudaStreamNonBlocking) == cudaSuccess) &&
                   (cudaEventCreateWithFlags(&g_evFork, cudaEventDisableTiming) == cudaSuccess) &&
                   (cudaEventCreateWithFlags(&g_evJoin, cudaEventDisableTiming) == cudaSuccess);
    }
} g_forkInit;
}

// ---------------- PTX helpers ----------------
__device__ __forceinline__ uint32_t smem_u32(const void* p) {
    uint32_t a;
    asm("{ .reg .u64 t; cvta.to.shared.u64 t, %1; cvt.u32.u64 %0, t; }" : "=r"(a) : "l"(p));
    return a;
}
__device__ __forceinline__ void wait_flag(const int* p, int target) {
    int v;
    do {
        asm volatile("ld.acquire.gpu.global.b32 %0, [%1];" : "=r"(v) : "l"(p) : "memory");
        if (v < target) __nanosleep(256);
    } while (v < target);
}
#if HAS_TC
__device__ __forceinline__ uint32_t elect_one() {
    uint32_t p;
    asm volatile("{ .reg .pred p; elect.sync _|p, 0xFFFFFFFF; selp.b32 %0,1,0,p; }" : "=r"(p));
    return p;
}
#define MBAR_INIT(addr, cnt) \
    asm volatile("mbarrier.init.shared.b64 [%0], %1;" :: "r"(addr), "r"(cnt) : "memory")
#define MBAR_WAIT(addr, par) do {                                              \
    uint32_t _m = (addr), _p = (par), _d;                                      \
    asm volatile("{ .reg .pred p; mbarrier.try_wait.parity.acquire.cta.shared::cta.b64 p, [%1], %2; selp.b32 %0,1,0,p; }" \
        : "=r"(_d) : "r"(_m), "r"(_p) : "memory");                             \
    if (!_d) {                                                                 \
        asm volatile("{ .reg .pred P1; WL%=: mbarrier.try_wait.parity.acquire.cta.shared::cta.b64 P1, [%0], %1, 0x989680; @P1 bra.uni WD%=; bra.uni WL%=; WD%=: }" \
            :: "r"(_m), "r"(_p) : "memory");                                   \
    } } while (0)
#define TC_COMMIT(addr) \
    asm volatile("tcgen05.commit.cta_group::1.mbarrier::arrive::one.shared::cluster.b64 [%0];" :: "r"(addr) : "memory")
#define TC_ALLOC(saddr, n) \
    asm volatile("tcgen05.alloc.cta_group::1.sync.aligned.shared::cta.b32 [%0], %1;" :: "r"(saddr), "r"(n) : "memory")
#define TC_DEALLOC(t, n) \
    asm volatile("tcgen05.dealloc.cta_group::1.sync.aligned.b32 %0, %1;" :: "r"(t), "r"(n))
#define TC_RELINQ() asm volatile("tcgen05.relinquish_alloc_permit.cta_group::1.sync.aligned;")
#define TC_WAIT_LD() asm volatile("tcgen05.wait::ld.sync.aligned;" ::: "memory")
#define TC_FENCE_AFTER() asm volatile("tcgen05.fence::after_thread_sync;" ::: "memory")

#define TC_LD_X32(r, ta)                                                        \
    asm volatile("tcgen05.ld.sync.aligned.32x32b.x32.b32 "                      \
        "{%0,%1,%2,%3,%4,%5,%6,%7,%8,%9,%10,%11,%12,%13,%14,%15,"               \
        "%16,%17,%18,%19,%20,%21,%22,%23,%24,%25,%26,%27,%28,%29,%30,%31}, [%32];" \
        : "=r"((r)[0]),"=r"((r)[1]),"=r"((r)[2]),"=r"((r)[3]),                  \
          "=r"((r)[4]),"=r"((r)[5]),"=r"((r)[6]),"=r"((r)[7]),                  \
          "=r"((r)[8]),"=r"((r)[9]),"=r"((r)[10]),"=r"((r)[11]),                \
          "=r"((r)[12]),"=r"((r)[13]),"=r"((r)[14]),"=r"((r)[15]),              \
          "=r"((r)[16]),"=r"((r)[17]),"=r"((r)[18]),"=r"((r)[19]),              \
          "=r"((r)[20]),"=r"((r)[21]),"=r"((r)[22]),"=r"((r)[23]),              \
          "=r"((r)[24]),"=r"((r)[25]),"=r"((r)[26]),"=r"((r)[27]),              \
          "=r"((r)[28]),"=r"((r)[29]),"=r"((r)[30]),"=r"((r)[31])               \
        : "r"(ta))

static constexpr uint64_t DESC_BASE_SW128 =
    (uint64_t(2) << 61) | (uint64_t(1) << 46) | (uint64_t(64) << 32) | (uint64_t(1) << 16);
__device__ __forceinline__ uint64_t mk_desc(uint32_t a) {
    return DESC_BASE_SW128 | ((uint64_t)(a >> 4) & 0x3FFF);
}
__device__ __forceinline__ void mma_f16_ss(uint32_t d, uint64_t ad, uint64_t bd,
                                           uint32_t idesc, bool acc) {
    uint32_t en = acc ? 1u : 0u;
    asm volatile(
        "{ .reg .pred p; setp.ne.u32 p, %4, 0;\n\t"
        "tcgen05.mma.cta_group::1.kind::f16 [%0], %1, %2, %3, {%5,%5,%5,%5}, p; }"
        :: "r"(d), "l"(ad), "l"(bd), "r"(idesc), "r"(en), "r"(0u) : "memory");
}
__device__ __forceinline__ void cp16(uint32_t dst, const void* src) {
    asm volatile("cp.async.cg.shared.global [%0], [%1], 16;" :: "r"(dst), "l"(src));
}
#define CP_ARRIVE(addr) \
    asm volatile("cp.async.mbarrier.arrive.noinc.shared.b64 [%0];" :: "r"(addr) : "memory")
#endif  // HAS_TC

// ---------------------------------------------------------------------------
// Kernel A: bias + flag reset (stream-ordered before the fork).
// ---------------------------------------------------------------------------
__global__ void build_bias(const float* __restrict__ P, const float* __restrict__ coef,
                           float* __restrict__ out, int n) {
    if (blockIdx.x == 0 && threadIdx.x < 8) g_flagW[threadIdx.x] = 0;
    __shared__ float c[ID_DIM];
    if (threadIdx.x < ID_DIM) c[threadIdx.x] = coef[threadIdx.x];
    __syncthreads();
    int i = blockIdx.x * blockDim.x + threadIdx.x;
    if (i >= n) return;
    const float4* row = reinterpret_cast<const float4*>(P + (size_t)i * ID_DIM);
    float acc = 0.f;
#pragma unroll
    for (int j = 0; j < 16; ++j) {
        float4 v = row[j];
        acc += v.x * c[4 * j] + v.y * c[4 * j + 1] + v.z * c[4 * j + 2] + v.w * c[4 * j + 3];
    }
    out[i] = acc;
}

// ---------------------------------------------------------------------------
// Kernel B (builder): W hi/lo, grouped for ordered completion.
// Grid = 8 groups x 512 CTAs (ascending bid => group g finishes ~in order).
// Group g covers W elements [g*524288, (g+1)*524288) (= 256 N-rows x 2048 K).
// ---------------------------------------------------------------------------
__global__ __launch_bounds__(256)
void build_W_groups(const float* __restrict__ P, const float* __restrict__ coef,
                    __nv_bfloat16* __restrict__ whi, __nv_bfloat16* __restrict__ wlo) {
    __shared__ float c[ID_DIM];
    if (threadIdx.x < ID_DIM) c[threadIdx.x] = coef[threadIdx.x];
    __syncthreads();
    const int g   = blockIdx.x >> 9;         // 0..7
    const int sub = blockIdx.x & 511;        // 0..511
    const int tid = threadIdx.x;
    const int q = (tid & 15) * 4;
    const size_t gBaseElem = (size_t)g * 524288;           // W elems
    const float4* P4 = reinterpret_cast<const float4*>(P) + gBaseElem * 16;
    const int S = BUILD_CTAS_PER_GROUP * 256;              // 131072 f4 / pass
    // slice = 8,388,608 f4; 64 passes/thread, unrolled 4 (MLP=4)
    int idx = sub * 256 + tid;
    for (int it = 0; it < 64; it += 4, idx += 4 * S) {
        float p[4];
#pragma unroll
        for (int u = 0; u < 4; ++u) {
            float4 v = P4[idx + u * S];
            p[u] = v.x * c[q] + v.y * c[q + 1] + v.z * c[q + 2] + v.w * c[q + 3];
        }
#pragma unroll
        for (int d = 8; d >= 1; d >>= 1) {
            p[0] += __shfl_xor_sync(0xffffffffu, p[0], d);
            p[1] += __shfl_xor_sync(0xffffffffu, p[1], d);
            p[2] += __shfl_xor_sync(0xffffffffu, p[2], d);
            p[3] += __shfl_xor_sync(0xffffffffu, p[3], d);
        }
        if ((tid & 15) == 0) {
#pragma unroll
            for (int u = 0; u < 4; ++u) {
                size_t widx = gBaseElem + (size_t)((idx + u * S) >> 4);
                __nv_bfloat16 h = __float2bfloat16_rn(p[u]);
                whi[widx] = h;
                wlo[widx] = __float2bfloat16_rn(p[u] - __bfloat162float(h));
            }
        }
    }
    __threadfence();
    __syncthreads();
    if (tid == 0) atomicAdd(&g_flagW[g], 1);
}

// ---------------------------------------------------------------------------
// Kernel C: split x into bf16 hi/lo (runs on the GEMM branch, overlaps build).
// ---------------------------------------------------------------------------
__global__ void split_x(const float* __restrict__ x, __nv_bfloat16* __restrict__ hi,
                        __nv_bfloat16* __restrict__ lo, int n8) {
    int i = blockIdx.x * blockDim.x + threadIdx.x;
    if (i >= n8) return;
    const float4* xp = reinterpret_cast<const float4*>(x);
    float4 a = xp[2 * i], b = xp[2 * i + 1];
    float v[8] = {a.x, a.y, a.z, a.w, b.x, b.y, b.z, b.w};
    uint32_t uh[4], ul[4];
#pragma unroll
    for (int j = 0; j < 4; ++j) {
        __nv_bfloat16 h0 = __float2bfloat16_rn(v[2 * j]);
        __nv_bfloat16 h1 = __float2bfloat16_rn(v[2 * j + 1]);
        __nv_bfloat16 l0 = __float2bfloat16_rn(v[2 * j] - __bfloat162float(h0));
        __nv_bfloat16 l1 = __float2bfloat16_rn(v[2 * j + 1] - __bfloat162float(h1));
        uh[j] = ((uint32_t)__bfloat16_as_ushort(h1) << 16) | __bfloat16_as_ushort(h0);
        ul[j] = ((uint32_t)__bfloat16_as_ushort(l1) << 16) | __bfloat16_as_ushort(l0);
    }
    reinterpret_cast<uint4*>(hi)[i] = make_uint4(uh[0], uh[1], uh[2], uh[3]);
    reinterpret_cast<uint4*>(lo)[i] = make_uint4(ul[0], ul[1], ul[2], ul[3]);
}

// ---------------------------------------------------------------------------
// Kernel D: GEMM 128x256 tiles, warp-specialized, 2-stage pipeline (R6 body).
// Producers gate once on their bn-group flag (builder runs concurrently).
// ---------------------------------------------------------------------------
#define BM 128
#define BN 256
#define KC 64
#define NCHUNK (DIM_K / KC)          // 32
#define A_TILE 16384
#define B_TILE 32768
#define STAGE_B (2 * A_TILE + 2 * B_TILE)   // 96 KB
#define SM_MBAR 16                   // full0 +0, full1 +8, mdone0 +16, mdone1 +24, alldone +32
#define SM_STAGE 1024
#define GEMM_SMEM (SM_STAGE + 2 * STAGE_B)   // 197632

__global__ __launch_bounds__(256, 1)
void gemm_tc(const __nv_bfloat16* __restrict__ Xhi, const __nv_bfloat16* __restrict__ Xlo,
             const __nv_bfloat16* __restrict__ Whi, const __nv_bfloat16* __restrict__ Wlo,
             const float* __restrict__ bias, float* __restrict__ C) {
    extern __shared__ char smem[];
    const int tid = threadIdx.x, wid = tid >> 5, lane = tid & 31;
    const int bn = blockIdx.x, bm = blockIdx.y;

#if HAS_TC
    const uint32_t sbase = smem_u32(smem);
    if (wid == 0) {
        TC_ALLOC(sbase, 256);
        TC_RELINQ();
    }
    if (tid == 0) {
        MBAR_INIT(sbase + SM_MBAR + 0, 128);   // full[0]
        MBAR_INIT(sbase + SM_MBAR + 8, 128);   // full[1]
        MBAR_INIT(sbase + SM_MBAR + 16, 1);    // mdone[0]
        MBAR_INIT(sbase + SM_MBAR + 24, 1);    // mdone[1]
        MBAR_INIT(sbase + SM_MBAR + 32, 1);    // alldone
    }
    __syncthreads();
    uint32_t tmem;
    asm volatile("ld.shared.b32 %0, [%1];" : "=r"(tmem) : "r"(sbase));

    const __nv_bfloat16* Ah = Xhi + (size_t)bm * BM * DIM_K;
    const __nv_bfloat16* Al = Xlo + (size_t)bm * BM * DIM_K;
    const __nv_bfloat16* Bh = Whi + (size_t)bn * BN * DIM_K;
    const __nv_bfloat16* Bl = Wlo + (size_t)bn * BN * DIM_K;

    if (wid == 0) {
        // ---------------- consumer: MMA issue ----------------
        if (elect_one()) {
            const uint32_t idesc =
                (1u << 4) | (1u << 7) | (1u << 10) | ((BN / 8) << 17) | ((BM / 16) << 24);
            int fph[2] = {0, 0};
            bool first = true;
            for (int i = 0; i < NCHUNK; ++i) {
                const int s = i & 1;
                MBAR_WAIT(sbase + SM_MBAR + 8 * s, fph[s]);
                fph[s] ^= 1;
                asm volatile("fence.proxy.async.shared::cta;" ::: "memory");
                const uint32_t stg = sbase + SM_STAGE + s * STAGE_B;
                uint64_t dAh = mk_desc(stg);
                uint64_t dAl = mk_desc(stg + A_TILE);
                uint64_t dBh = mk_desc(stg + 2 * A_TILE);
                uint64_t dBl = mk_desc(stg + 2 * A_TILE + B_TILE);
                uint64_t ad[3] = {dAh, dAh, dAl};
                uint64_t bd[3] = {dBh, dBl, dBh};
#pragma unroll
                for (int m = 0; m < 3; ++m)
#pragma unroll
                    for (int ks = 0; ks < 4; ++ks) {
                        mma_f16_ss(tmem, ad[m] + ks * 2, bd[m] + ks * 2, idesc, !first);
                        first = false;
                    }
                TC_COMMIT(sbase + SM_MBAR + 16 + 8 * s);
            }
            TC_COMMIT(sbase + SM_MBAR + 32);
            MBAR_WAIT(sbase + SM_MBAR + 32, 0);
        }
    } else if (wid <= 4) {
        // ---------------- producers: 4 warps (128 threads) ----------------
        if (lane == 0) wait_flag(&g_flagW[bn >> 0], BUILD_CTAS_PER_GROUP);
        __syncwarp();
        const int ptid = tid - 32;
        int dph[2] = {0, 0};
        for (int i = 0; i < NCHUNK; ++i) {
            const int s = i & 1;
            if (i >= 2) {
                MBAR_WAIT(sbase + SM_MBAR + 16 + 8 * s, dph[s]);
                dph[s] ^= 1;
            }
            const int k0 = i * KC;
            const uint32_t stg = sbase + SM_STAGE + s * STAGE_B;
#pragma unroll
            for (int t = 0; t < 8; ++t) {       // A_hi
                int cid = ptid + t * 128;
                int r = cid >> 3, cc = cid & 7;
                uint32_t off = (uint32_t)(r * 128 + cc * 16);
                cp16(stg + (off ^ ((off >> 3) & 0x70)), Ah + (size_t)r * DIM_K + k0 + cc * 8);
            }
#pragma unroll
            for (int t = 0; t < 8; ++t) {       // A_lo
                int cid = ptid + t * 128;
                int r = cid >> 3, cc = cid & 7;
                uint32_t off = (uint32_t)(r * 128 + cc * 16);
                cp16(stg + A_TILE + (off ^ ((off >> 3) & 0x70)),
                     Al + (size_t)r * DIM_K + k0 + cc * 8);
            }
#pragma unroll
            for (int t = 0; t < 16; ++t) {      // B_hi
                int cid = ptid + t * 128;
                int r = cid >> 3, cc = cid & 7;
                uint32_t off = (uint32_t)(r * 128 + cc * 16);
                cp16(stg + 2 * A_TILE + (off ^ ((off >> 3) & 0x70)),
                     Bh + (size_t)r * DIM_K + k0 + cc * 8);
            }
#pragma unroll
            for (int t = 0; t < 16; ++t) {      // B_lo
                int cid = ptid + t * 128;
                int r = cid >> 3, cc = cid & 7;
                uint32_t off = (uint32_t)(r * 128 + cc * 16);
                cp16(stg + 2 * A_TILE + B_TILE + (off ^ ((off >> 3) & 0x70)),
                     Bl + (size_t)r * DIM_K + k0 + cc * 8);
            }
            CP_ARRIVE(sbase + SM_MBAR + 8 * s);
        }
    }
    __syncthreads();
    TC_FENCE_AFTER();

    // Epilogue: warps 0-3; 8 col-blocks of 32.
    if (wid < 4) {
        float* tbuf = reinterpret_cast<float*>(smem + SM_STAGE + wid * 32 * 33 * 4);
        float* Cb = C + ((size_t)bm * BM) * DIM_N + bn * BN;
        const int rsub = wid * 32;
#pragma unroll 1
        for (int sub = 0; sub < 8; ++sub) {
            const int cb = sub * 32;
            uint32_t regs[32];
            TC_LD_X32(regs, tmem + cb);
            TC_WAIT_LD();
#pragma unroll
            for (int j = 0; j < 32; ++j) tbuf[lane * 33 + j] = __uint_as_float(regs[j]);
            __syncwarp();
            const float bv = bias[bn * BN + cb + lane];
#pragma unroll
            for (int r = 0; r < 32; ++r)
                Cb[(size_t)(rsub + r) * DIM_N + cb + lane] = tbuf[r * 33 + lane] + bv;
            __syncwarp();
        }
    }
    __syncthreads();
    if (wid == 0) TC_DEALLOC(tmem, 256);

#else  // ------------------- SIMT fallback (never runs on GB300) ------------
    if (tid == 0) wait_flag(&g_flagW[bn], BUILD_CTAS_PER_GROUP);
    __syncthreads();
    constexpr int K = DIM_K;
    float (*As)[132] = reinterpret_cast<float(*)[132]>(smem);
    float (*Bs)[132] = reinterpret_cast<float(*)[132]>(smem + 16 * 132 * sizeof(float));
    const int ty = tid >> 4, tx = tid & 15;
    const int lr = tid >> 1;
    const int kof = (tid & 1) * 8;

    for (int half = 0; half < 2; ++half) {
        const __nv_bfloat16* Ah = Xhi + (size_t)bm * BM * K;
        const __nv_bfloat16* Al = Xlo + (size_t)bm * BM * K;
        const __nv_bfloat16* Bh = Whi + ((size_t)bn * BN + half * 128) * K;
        const __nv_bfloat16* Bl = Wlo + ((size_t)bn * BN + half * 128) * K;
        float acc[8][8] = {};
        for (int k0 = 0; k0 < K; k0 += 16) {
            uint4 vh = *reinterpret_cast<const uint4*>(Ah + (size_t)lr * K + k0 + kof);
            uint4 vl = *reinterpret_cast<const uint4*>(Al + (size_t)lr * K + k0 + kof);
#pragma unroll
            for (int w = 0; w < 4; ++w) {
                float2 h = __bfloat1622float2(reinterpret_cast<const __nv_bfloat162*>(&vh)[w]);
                float2 l = __bfloat1622float2(reinterpret_cast<const __nv_bfloat162*>(&vl)[w]);
                As[kof + 2 * w + 0][lr] = h.x + l.x;
                As[kof + 2 * w + 1][lr] = h.y + l.y;
            }
            vh = *reinterpret_cast<const uint4*>(Bh + (size_t)lr * K + k0 + kof);
            vl = *reinterpret_cast<const uint4*>(Bl + (size_t)lr * K + k0 + kof);
#pragma unroll
            for (int w = 0; w < 4; ++w) {
                float2 h = __bfloat1622float2(reinterpret_cast<const __nv_bfloat162*>(&vh)[w]);
                float2 l = __bfloat1622float2(reinterpret_cast<const __nv_bfloat162*>(&vl)[w]);
                Bs[kof + 2 * w + 0][lr] = h.x + l.x;
                Bs[kof + 2 * w + 1][lr] = h.y + l.y;
            }
            __syncthreads();
#pragma unroll
            for (int kk = 0; kk < 16; ++kk) {
                float4 a0 = *reinterpret_cast<const float4*>(&As[kk][ty * 8 + 0]);
                float4 a1 = *reinterpret_cast<const float4*>(&As[kk][ty * 8 + 4]);
                float4 b0 = *reinterpret_cast<const float4*>(&Bs[kk][tx * 8 + 0]);
                float4 b1 = *reinterpret_cast<const float4*>(&Bs[kk][tx * 8 + 4]);
                float af[8] = {a0.x, a0.y, a0.z, a0.w, a1.x, a1.y, a1.z, a1.w};
                float bf[8] = {b0.x, b0.y, b0.z, b0.w, b1.x, b1.y, b1.z, b1.w};
#pragma unroll
                for (int i = 0; i < 8; ++i)
#pragma unroll
                    for (int j = 0; j < 8; ++j)
                        acc[i][j] += af[i] * bf[j];
            }
            __syncthreads();
        }
#pragma unroll
        for (int i = 0; i < 8; ++i) {
            const int row = bm * BM + ty * 8 + i;
            float* Crow = C + (size_t)row * DIM_N + bn * BN + half * 128 + tx * 8;
            const float* brow = bias + bn * BN + half * 128 + tx * 8;
#pragma unroll
            for (int j4 = 0; j4 < 2; ++j4) {
                float4 v;
                v.x = acc[i][j4 * 4 + 0] + brow[j4 * 4 + 0];
                v.y = acc[i][j4 * 4 + 1] + brow[j4 * 4 + 1];
                v.z = acc[i][j4 * 4 + 2] + brow[j4 * 4 + 2];
                v.w = acc[i][j4 * 4 + 3] + brow[j4 * 4 + 3];
                *reinterpret_cast<float4*>(Crow + j4 * 4) = v;
            }
        }
        __syncthreads();
    }
#endif
}

// ---------------------------------------------------------------------------
extern "C" void kernel_launch(void* const* d_in, const int* in_sizes, int n_in,
                              void* d_out, int out_size) {
    const float* x     = (const float*)d_in[0];
    const float* P_w   = (const float*)d_in[1];
    const float* P_b   = (const float*)d_in[2];
    const float* wcoef = (const float*)d_in[3];
    const float* bcoef = (const float*)d_in[4];
    float* out = (float*)d_out;

    __nv_bfloat16 *Whi, *Wlo, *Xhi, *Xlo;
    float* bias;
    cudaGetSymbolAddress((void**)&Whi, g_Whi);
    cudaGetSymbolAddress((void**)&Wlo, g_Wlo);
    cudaGetSymbolAddress((void**)&Xhi, g_Xhi);
    cudaGetSymbolAddress((void**)&Xlo, g_Xlo);
    cudaGetSymbolAddress((void**)&bias, g_bias);

    cudaFuncSetAttribute(gemm_tc, cudaFuncAttributeMaxDynamicSharedMemorySize, GEMM_SMEM);

    dim3 ggrid(DIM_N / BN, BATCH_M / BM);   // (8 bn, 64 bm)
    const int nsplit = (BATCH_M * DIM_K / 8 + 255) / 256;

    // Flag reset + bias, stream-ordered before both branches.
    build_bias<<<8, 256>>>(P_b, bcoef, bias, DIM_N);

    if (g_forkOK) {
        // Fork: branch 2 (split_x -> gemm) runs concurrently with the builder.
        cudaEventRecord(g_evFork, 0);
        cudaStreamWaitEvent(g_s2, g_evFork, 0);

        build_W_groups<<<8 * BUILD_CTAS_PER_GROUP, 256>>>(P_w, wcoef, Whi, Wlo);  // branch 1

        split_x<<<nsplit, 256, 0, g_s2>>>(x, Xhi, Xlo, BATCH_M * DIM_K / 8);      // branch 2
        gemm_tc<<<ggrid, 256, GEMM_SMEM, g_s2>>>(Xhi, Xlo, Whi, Wlo, bias, out);

        cudaEventRecord(g_evJoin, g_s2);
        cudaStreamWaitEvent(0, g_evJoin, 0);
    } else {
        // Serial fallback (still correct: flags complete before gemm runs).
        build_W_groups<<<8 * BUILD_CTAS_PER_GROUP, 256>>>(P_w, wcoef, Whi, Wlo);
        split_x<<<nsplit, 256>>>(x, Xhi, Xlo, BATCH_M * DIM_K / 8);
        gemm_tc<<<ggrid, 256, GEMM_SMEM>>>(Xhi, Xlo, Whi, Wlo, bias, out);
    }

    (void)in_sizes; (void)n_in; (void)out_size;
}